// round 13
// baseline (speedup 1.0000x reference)
#include <cuda_runtime.h>
#include <cuda_fp16.h>
#include <cstdint>
#include <cstddef>

#define HEADS    16
#define HD       128
#define IN_DIM   1024
#define OUT_DIM  1024
#define QKV_DIM  6144
#define MAX_B    32768

// ---------------- scratch (__device__ globals; allocation-free rule) -------
__device__ __half g_qkv [(size_t)MAX_B * QKV_DIM];   // 384 MB
__device__ __half g_sh  [(size_t)MAX_B * HD];        // 8 MB
__device__ __half g_xh  [(size_t)MAX_B * IN_DIM];    // 64 MB
__device__ __half g_wth [(size_t)QKV_DIM * IN_DIM];  // 12 MB   W_pre^T
__device__ __half g_wpth[(size_t)OUT_DIM * HD];      // 256 KB  W_proj^T

// ---------------- helpers ----------------------------------------------------
__device__ __forceinline__ void cp_async16(void* s, const void* g) {
    uint32_t a = (uint32_t)__cvta_generic_to_shared(s);
    asm volatile("cp.async.cg.shared.global [%0], [%1], 16;\n" :: "r"(a), "l"(g));
}
__device__ __forceinline__ void cp_commit() { asm volatile("cp.async.commit_group;\n" ::); }
template <int N>
__device__ __forceinline__ void cp_wait() { asm volatile("cp.async.wait_group %0;\n" :: "n"(N)); }

__device__ __forceinline__ void mma_f16(float c[4], const uint32_t a[4], const uint32_t b[2]) {
    asm volatile(
        "mma.sync.aligned.m16n8k16.row.col.f32.f16.f16.f32 "
        "{%0,%1,%2,%3}, {%4,%5,%6,%7}, {%8,%9}, {%0,%1,%2,%3};\n"
        : "+f"(c[0]), "+f"(c[1]), "+f"(c[2]), "+f"(c[3])
        : "r"(a[0]), "r"(a[1]), "r"(a[2]), "r"(a[3]),
          "r"(b[0]), "r"(b[1]));
}

__device__ __forceinline__ void ldsm_x4(uint32_t r[4], const void* p) {
    uint32_t a = (uint32_t)__cvta_generic_to_shared(p);
    asm volatile("ldmatrix.sync.aligned.m8n8.x4.shared.b16 {%0,%1,%2,%3}, [%4];"
                 : "=r"(r[0]), "=r"(r[1]), "=r"(r[2]), "=r"(r[3]) : "r"(a));
}

// ---------------------------------------------------------------------------
// fp16 GEMM: CTA 256x128, 512 threads, 16 warps (4m x 4n), warp tile 64x32,
// BK=64, pitch-72 smem, ldmatrix.x4, 2-stage pipeline (R9 structure).
// 32 warps/SM (2 CTA) AND lower smem bytes/FLOP than R9.
// ---------------------------------------------------------------------------
#define BM   256
#define BN   128
#define BK   64
#define BKP  72
#define A_ST (BM * BKP)                       // halves per A stage (18432)
#define B_ST (BN * BKP)                       // 9216
#define GEMM_SMEM (2 * (A_ST + B_ST) * 2)     // 110592 B (x2 CTA = 221 KB/SM)

template <typename OutT>
__global__ void __launch_bounds__(512, 2)
gemm_f16_kernel(const __half* __restrict__ A, const __half* __restrict__ Bt,
                const float* __restrict__ bias, float bias_scale,
                OutT* __restrict__ C, int M, int N, int K)
{
    extern __shared__ __half smem[];
    __half* As = smem;                // [2][BM][BKP]
    __half* Bs = smem + 2 * A_ST;     // [2][BN][BKP]

    const int tid  = threadIdx.x;
    const int lane = tid & 31;
    const int warp = tid >> 5;
    const int wm   = warp & 3;    // 4 x 64-row warp tiles
    const int wn   = warp >> 2;   // 4 x 32-col warp tiles

    const int m0 = blockIdx.y * BM;
    const int n0 = blockIdx.x * BN;

    float acc[4][4][4];   // [mi][ni][frag]
    #pragma unroll
    for (int i = 0; i < 4; i++)
        #pragma unroll
        for (int j = 0; j < 4; j++)
            #pragma unroll
            for (int r = 0; r < 4; r++) acc[i][j][r] = 0.0f;

    // loader: A 2048 chunks (4/thread), B 1024 chunks (2/thread); 16B chunks
    #define LOAD_TILE(s, k0) do {                                                  \
        __half* as = As + (s) * A_ST;                                              \
        __half* bs = Bs + (s) * B_ST;                                              \
        _Pragma("unroll")                                                          \
        for (int i = 0; i < 4; i++) {                                              \
            const int c = tid + i * 512;                                           \
            const int row = c >> 3, col = (c & 7) * 8;                             \
            cp_async16(as + row * BKP + col, A + (size_t)(m0 + row) * K + (k0) + col); \
        }                                                                          \
        _Pragma("unroll")                                                          \
        for (int i = 0; i < 2; i++) {                                              \
            const int c = tid + i * 512;                                           \
            const int row = c >> 3, col = (c & 7) * 8;                             \
            cp_async16(bs + row * BKP + col, Bt + (size_t)(n0 + row) * K + (k0) + col); \
        }                                                                          \
        cp_commit();                                                               \
    } while (0)

    const int KT = K / BK;   // 16 (K1) / 2 (K3)
    LOAD_TILE(0, 0);
    LOAD_TILE(1, BK);
    cp_wait<1>();            // stage 0 landed
    __syncthreads();

    // fragment addressing (conflict-free at pitch 72, proven pattern)
    const int fa_row = wm * 64 + (lane & 15);                      // + mi*16
    const int fa_col = (lane >> 4) * 8;                            // + ks*16
    const int fb_row = wn * 32 + ((lane >> 4) << 3) + (lane & 7);  // + pi*16
    const int fb_col = ((lane >> 3) & 1) * 8;                      // + ks*16

    for (int it = 0; it < KT; it++) {
        const int buf = it & 1;
        const __half* as = As + buf * A_ST;
        const __half* bs = Bs + buf * B_ST;

        #pragma unroll
        for (int ks = 0; ks < 4; ks++) {
            uint32_t af[4][4];
            #pragma unroll
            for (int mi = 0; mi < 4; mi++)
                ldsm_x4(af[mi], as + (fa_row + mi * 16) * BKP + fa_col + ks * 16);

            uint32_t bfr[2][4];   // bfr[pi] = {b[2pi][0..1], b[2pi+1][0..1]}
            #pragma unroll
            for (int pi = 0; pi < 2; pi++)
                ldsm_x4(bfr[pi], bs + (fb_row + pi * 16) * BKP + fb_col + ks * 16);

            #pragma unroll
            for (int mi = 0; mi < 4; mi++)
                #pragma unroll
                for (int ni = 0; ni < 4; ni++)
                    mma_f16(acc[mi][ni], af[mi], &bfr[ni >> 1][(ni & 1) * 2]);
        }

        if (it + 1 < KT) {
            cp_wait<0>();        // stage it+1 landed (had a full iter)
            __syncthreads();     // visible + all reads of buf done
            if (it + 2 < KT) LOAD_TILE(buf, (it + 2) * BK);
        }
    }
    #undef LOAD_TILE

    // epilogue (bias hoisted)
    float bc[4][2];
    #pragma unroll
    for (int ni = 0; ni < 4; ni++) {
        const int col = n0 + wn * 32 + ni * 8 + (lane & 3) * 2;
        bc[ni][0] = bias_scale * __ldg(&bias[col]);
        bc[ni][1] = bias_scale * __ldg(&bias[col + 1]);
    }
    #pragma unroll
    for (int mi = 0; mi < 4; mi++) {
        const int row = m0 + wm * 64 + mi * 16 + (lane >> 2);
        #pragma unroll
        for (int ni = 0; ni < 4; ni++) {
            const int col = n0 + wn * 32 + ni * 8 + (lane & 3) * 2;
            if constexpr (sizeof(OutT) == 2) {
                *(__half2*)&C[(size_t)row * N + col] =
                    __floats2half2_rn(acc[mi][ni][0] + bc[ni][0], acc[mi][ni][1] + bc[ni][1]);
                *(__half2*)&C[(size_t)(row + 8) * N + col] =
                    __floats2half2_rn(acc[mi][ni][2] + bc[ni][0], acc[mi][ni][3] + bc[ni][1]);
            } else {
                C[(size_t)row * N + col]           = acc[mi][ni][0] + bc[ni][0];
                C[(size_t)row * N + col + 1]       = acc[mi][ni][1] + bc[ni][1];
                C[(size_t)(row + 8) * N + col]     = acc[mi][ni][2] + bc[ni][0];
                C[(size_t)(row + 8) * N + col + 1] = acc[mi][ni][3] + bc[ni][1];
            }
        }
    }
}

// ---------------- fp32 -> fp16 convert --------------------------------------
__global__ void __launch_bounds__(256)
f2h_kernel(const float* __restrict__ in, __half* __restrict__ out, int n8)
{
    for (int i = blockIdx.x * blockDim.x + threadIdx.x; i < n8; i += gridDim.x * blockDim.x) {
        const float4 v0 = ((const float4*)in)[i * 2];
        const float4 v1 = ((const float4*)in)[i * 2 + 1];
        __half2 h[4];
        h[0] = __floats2half2_rn(v0.x, v0.y);
        h[1] = __floats2half2_rn(v0.z, v0.w);
        h[2] = __floats2half2_rn(v1.x, v1.y);
        h[3] = __floats2half2_rn(v1.z, v1.w);
        ((uint4*)out)[i] = *(uint4*)h;
    }
}

// ---------------- transpose + fp16 convert ----------------------------------
__global__ void __launch_bounds__(256)
transpose_h_kernel(const float* __restrict__ in, __half* __restrict__ out, int R, int Cc)
{
    __shared__ float t[32][33];
    const int tx = threadIdx.x & 31, ty = threadIdx.x >> 5;
    const int bx = blockIdx.x * 32, by = blockIdx.y * 32;
    #pragma unroll
    for (int j = 0; j < 4; j++)
        t[ty + j * 8][tx] = in[(size_t)(by + ty + j * 8) * Cc + bx + tx];
    __syncthreads();
    #pragma unroll
    for (int j = 0; j < 4; j++)
        out[(size_t)(bx + ty + j * 8) * R + by + tx] = __float2half_rn(t[tx][ty + j * 8]);
}

// ---------------------------------------------------------------------------
// K2: warp-per-token attention + head collapse (proven R8 version)
// ---------------------------------------------------------------------------
#define W_PART 2176
#define W_WB   6528
#define W_SZ   6560
#define ATTN_SMEM (4 * W_SZ * 2)    // 52480 B, 4 warps/CTA

__global__ void __launch_bounds__(128)
attn_kernel(const __half* __restrict__ qkv, __half* __restrict__ s_out)
{
    extern __shared__ __half asm_[];
    const int lane = threadIdx.x & 31;
    const int warp = threadIdx.x >> 5;
    const int tok  = blockIdx.x * 4 + warp;

    __half* base = asm_ + warp * W_SZ;
    const __half* src = qkv + (size_t)tok * QKV_DIM;

    #pragma unroll
    for (int i = 0; i < 24; i++) {
        const int c = i * 32 + lane;
        const int part = c >> 8;
        const int rem = c & 255, r = rem >> 4, j = rem & 15;
        cp_async16(base + part * W_PART + r * 136 + j * 8,
                   src + part * 2048 + r * 128 + j * 8);
    }
    cp_commit();
    cp_wait<0>();
    __syncwarp();

    float sacc[2][4] = {{0,0,0,0},{0,0,0,0}};
    const int a_row = lane & 15;
    const int a_col = (lane >> 4) * 8;
    const int b_row = ((lane >> 4) << 3) + (lane & 7);
    const int b_col = ((lane >> 3) & 1) * 8;
    #pragma unroll
    for (int ks = 0; ks < 8; ks++) {
        uint32_t af[4], bf[4];
        ldsm_x4(af, base + a_row * 136 + a_col + ks * 16);
        ldsm_x4(bf, base + W_PART + b_row * 136 + b_col + ks * 16);
        mma_f16(sacc[0], af, &bf[0]);
        mma_f16(sacc[1], af, &bf[2]);
    }

    const float scale = 0.08838834764831844f;
    float a0 = sacc[0][0] * scale, a1 = sacc[0][1] * scale;
    float a2 = sacc[1][0] * scale, a3 = sacc[1][1] * scale;
    float b0 = sacc[0][2] * scale, b1 = sacc[0][3] * scale;
    float b2 = sacc[1][2] * scale, b3 = sacc[1][3] * scale;

    float mA = fmaxf(fmaxf(a0, a1), fmaxf(a2, a3));
    float mB = fmaxf(fmaxf(b0, b1), fmaxf(b2, b3));
    #pragma unroll
    for (int off = 1; off <= 2; off <<= 1) {
        mA = fmaxf(mA, __shfl_xor_sync(0xffffffffu, mA, off));
        mB = fmaxf(mB, __shfl_xor_sync(0xffffffffu, mB, off));
    }
    a0 = __expf(a0 - mA); a1 = __expf(a1 - mA); a2 = __expf(a2 - mA); a3 = __expf(a3 - mA);
    b0 = __expf(b0 - mB); b1 = __expf(b1 - mB); b2 = __expf(b2 - mB); b3 = __expf(b3 - mB);
    float sA = a0 + a1 + a2 + a3, sB = b0 + b1 + b2 + b3;
    #pragma unroll
    for (int off = 1; off <= 2; off <<= 1) {
        sA += __shfl_xor_sync(0xffffffffu, sA, off);
        sB += __shfl_xor_sync(0xffffffffu, sB, off);
    }
    const float rA = __fdividef(1.0f, sA), rB = __fdividef(1.0f, sB);

    float cs0 = a0 * rA + b0 * rB;
    float cs1 = a1 * rA + b1 * rB;
    float cs2 = a2 * rA + b2 * rB;
    float cs3 = a3 * rA + b3 * rB;
    #pragma unroll
    for (int off = 4; off <= 16; off <<= 1) {
        cs0 += __shfl_xor_sync(0xffffffffu, cs0, off);
        cs1 += __shfl_xor_sync(0xffffffffu, cs1, off);
        cs2 += __shfl_xor_sync(0xffffffffu, cs2, off);
        cs3 += __shfl_xor_sync(0xffffffffu, cs3, off);
    }
    float* wb = (float*)(base + W_WB);
    if (lane < 4) {
        wb[2 * lane]     = cs0;
        wb[2 * lane + 1] = cs1;
        wb[8 + 2 * lane] = cs2;
        wb[9 + 2 * lane] = cs3;
    }
    __syncwarp();

    const __half2* V2 = (const __half2*)(base + 2 * W_PART);
    float2 o0 = {0.f, 0.f}, o1 = {0.f, 0.f};
    #pragma unroll
    for (int g = 0; g < 16; g++) {
        const float wg = wb[g];
        const float2 f0 = __half22float2(V2[g * 68 + lane]);
        const float2 f1 = __half22float2(V2[g * 68 + lane + 32]);
        o0.x += wg * f0.x; o0.y += wg * f0.y;
        o1.x += wg * f1.x; o1.y += wg * f1.y;
    }
    __half2* o = (__half2*)(s_out + (size_t)tok * HD);
    o[lane]      = __floats2half2_rn(o0.x, o0.y);
    o[lane + 32] = __floats2half2_rn(o1.x, o1.y);
}

// ---------------- launch ------------------------------------------------------
extern "C" void kernel_launch(void* const* d_in, const int* in_sizes, int n_in,
                              void* d_out, int out_size)
{
    const float* x      = (const float*)d_in[0];
    const float* W_pre  = (const float*)d_in[1];
    const float* b_pre  = (const float*)d_in[2];
    const float* W_proj = (const float*)d_in[3];
    const float* b_proj = (const float*)d_in[4];
    float* out = (float*)d_out;

    const int M = in_sizes[0] / IN_DIM;   // 32768

    __half *qkv, *sh, *xh, *wth, *wpth;
    cudaGetSymbolAddress((void**)&qkv,  g_qkv);
    cudaGetSymbolAddress((void**)&sh,   g_sh);
    cudaGetSymbolAddress((void**)&xh,   g_xh);
    cudaGetSymbolAddress((void**)&wth,  g_wth);
    cudaGetSymbolAddress((void**)&wpth, g_wpth);

    static bool attr_set = false;
    if (!attr_set) {
        cudaFuncSetAttribute(gemm_f16_kernel<__half>,
                             cudaFuncAttributeMaxDynamicSharedMemorySize, GEMM_SMEM);
        cudaFuncSetAttribute(gemm_f16_kernel<float>,
                             cudaFuncAttributeMaxDynamicSharedMemorySize, GEMM_SMEM);
        cudaFuncSetAttribute(attn_kernel,
                             cudaFuncAttributeMaxDynamicSharedMemorySize, ATTN_SMEM);
        attr_set = true;
    }

    // prep
    f2h_kernel<<<1024, 256>>>(x, xh, M * IN_DIM / 8);
    transpose_h_kernel<<<dim3(QKV_DIM / 32, IN_DIM / 32), 256>>>(W_pre, wth, IN_DIM, QKV_DIM);
    transpose_h_kernel<<<dim3(OUT_DIM / 32, HD / 32), 256>>>(W_proj, wpth, HD, OUT_DIM);

    // K1: qkv = x @ W_pre + b_pre            [M, 6144] half
    gemm_f16_kernel<__half><<<dim3(QKV_DIM / BN, M / BM), 512, GEMM_SMEM>>>(
        xh, wth, b_pre, 1.0f, qkv, M, QKV_DIM, IN_DIM);

    // K2: attention collapse -> s[M,128] (half), warp-per-token
    attn_kernel<<<M / 4, 128, ATTN_SMEM>>>(qkv, sh);

    // K3: out = s @ W_proj + 16*b_proj       [M, 1024] fp32
    gemm_f16_kernel<float><<<dim3(OUT_DIM / BN, M / BM), 512, GEMM_SMEM>>>(
        sh, wpth, b_proj, 16.0f, out, M, OUT_DIM, HD);
}

// round 14
// speedup vs baseline: 3.2938x; 3.2938x over previous
#include <cuda_runtime.h>
#include <cuda_fp16.h>
#include <cstdint>
#include <cstddef>

#define HEADS    16
#define HD       128
#define IN_DIM   1024
#define OUT_DIM  1024
#define QKV_DIM  6144
#define MAX_B    32768

// ---------------- scratch (__device__ globals; allocation-free rule) -------
__device__ __half g_qkv [(size_t)MAX_B * QKV_DIM];   // 384 MB
__device__ __half g_sh  [(size_t)MAX_B * HD];        // 8 MB
__device__ __half g_xh  [(size_t)MAX_B * IN_DIM];    // 64 MB
__device__ __half g_wth [(size_t)QKV_DIM * IN_DIM];  // 12 MB   W_pre^T
__device__ __half g_wpth[(size_t)OUT_DIM * HD];      // 256 KB  W_proj^T

// ---------------- helpers ----------------------------------------------------
__device__ __forceinline__ void cp_async16(void* s, const void* g) {
    uint32_t a = (uint32_t)__cvta_generic_to_shared(s);
    asm volatile("cp.async.cg.shared.global [%0], [%1], 16;\n" :: "r"(a), "l"(g));
}
__device__ __forceinline__ void cp_commit() { asm volatile("cp.async.commit_group;\n" ::); }
template <int N>
__device__ __forceinline__ void cp_wait() { asm volatile("cp.async.wait_group %0;\n" :: "n"(N)); }

// NON-volatile: pure register op; lets the scheduler interleave HMMAs with
// the next chunk's LDSMs (register deps still enforce producer order).
__device__ __forceinline__ void mma_f16(float c[4], const uint32_t a[4], const uint32_t b[2]) {
    asm("mma.sync.aligned.m16n8k16.row.col.f32.f16.f16.f32 "
        "{%0,%1,%2,%3}, {%4,%5,%6,%7}, {%8,%9}, {%0,%1,%2,%3};\n"
        : "+f"(c[0]), "+f"(c[1]), "+f"(c[2]), "+f"(c[3])
        : "r"(a[0]), "r"(a[1]), "r"(a[2]), "r"(a[3]),
          "r"(b[0]), "r"(b[1]));
}

__device__ __forceinline__ void ldsm_x4(uint32_t r[4], const void* p) {
    uint32_t a = (uint32_t)__cvta_generic_to_shared(p);
    asm volatile("ldmatrix.sync.aligned.m8n8.x4.shared.b16 {%0,%1,%2,%3}, [%4];"
                 : "=r"(r[0]), "=r"(r[1]), "=r"(r[2]), "=r"(r[3]) : "r"(a));
}

// ---------------------------------------------------------------------------
// fp16 GEMM (R9-proven): CTA 128x128, 8 warps (4m x 2n), warp 32x64, BK=64,
// pitch-72 smem, ldmatrix.x4, 2-stage pipeline, one sync+wait per iter.
// ---------------------------------------------------------------------------
#define BM   128
#define BN   128
#define BK   64
#define BKP  72
#define A_ST (BM * BKP)                       // halves per A stage (9216)
#define B_ST (BN * BKP)
#define GEMM_SMEM (2 * (A_ST + B_ST) * 2)     // 73728 B

template <typename OutT>
__global__ void __launch_bounds__(256, 2)
gemm_f16_kernel(const __half* __restrict__ A, const __half* __restrict__ Bt,
                const float* __restrict__ bias, float bias_scale,
                OutT* __restrict__ C, int M, int N, int K)
{
    extern __shared__ __half smem[];
    __half* As = smem;                // [2][BM][BKP]
    __half* Bs = smem + 2 * A_ST;     // [2][BN][BKP]

    const int tid  = threadIdx.x;
    const int lane = tid & 31;
    const int warp = tid >> 5;
    const int wm   = warp & 3;
    const int wn   = warp >> 2;

    const int m0 = blockIdx.y * BM;
    const int n0 = blockIdx.x * BN;

    float acc[2][8][4];
    #pragma unroll
    for (int i = 0; i < 2; i++)
        #pragma unroll
        for (int j = 0; j < 8; j++)
            #pragma unroll
            for (int r = 0; r < 4; r++) acc[i][j][r] = 0.0f;

    #define LOAD_TILE(s, k0) do {                                                  \
        __half* as = As + (s) * A_ST;                                              \
        __half* bs = Bs + (s) * B_ST;                                              \
        _Pragma("unroll")                                                          \
        for (int i = 0; i < 4; i++) {                                              \
            const int c = tid + i * 256;                                           \
            const int row = c >> 3, col = (c & 7) * 8;                             \
            cp_async16(as + row * BKP + col, A  + (size_t)(m0 + row) * K + (k0) + col); \
            cp_async16(bs + row * BKP + col, Bt + (size_t)(n0 + row) * K + (k0) + col); \
        }                                                                          \
        cp_commit();                                                               \
    } while (0)

    const int KT = K / BK;   // 16 (K1) / 2 (K3)
    LOAD_TILE(0, 0);
    LOAD_TILE(1, BK);
    cp_wait<1>();            // stage 0 landed
    __syncthreads();

    const int fa_row = wm * 32 + (lane & 15);
    const int fa_col = (lane >> 4) * 8;
    const int fb_row = wn * 64 + ((lane >> 4) << 3) + (lane & 7);
    const int fb_col = ((lane >> 3) & 1) * 8;

    for (int it = 0; it < KT; it++) {
        const int buf = it & 1;
        const __half* as = As + buf * A_ST;
        const __half* bs = Bs + buf * B_ST;

        #pragma unroll
        for (int ks = 0; ks < 4; ks++) {
            uint32_t af[2][4];
            #pragma unroll
            for (int mi = 0; mi < 2; mi++)
                ldsm_x4(af[mi], as + (fa_row + mi * 16) * BKP + fa_col + ks * 16);

            uint32_t bfr[4][4];
            #pragma unroll
            for (int pi = 0; pi < 4; pi++)
                ldsm_x4(bfr[pi], bs + (fb_row + pi * 16) * BKP + fb_col + ks * 16);

            #pragma unroll
            for (int mi = 0; mi < 2; mi++)
                #pragma unroll
                for (int ni = 0; ni < 8; ni++)
                    mma_f16(acc[mi][ni], af[mi], &bfr[ni >> 1][(ni & 1) * 2]);
        }

        if (it + 1 < KT) {
            cp_wait<0>();        // stage it+1 landed (had a full iter)
            __syncthreads();     // visible + all reads of buf done
            if (it + 2 < KT) LOAD_TILE(buf, (it + 2) * BK);
        }
    }
    #undef LOAD_TILE

    // epilogue: streaming stores (evict-first), bias hoisted
    float bc[8][2];
    #pragma unroll
    for (int ni = 0; ni < 8; ni++) {
        const int col = n0 + wn * 64 + ni * 8 + (lane & 3) * 2;
        bc[ni][0] = bias_scale * __ldg(&bias[col]);
        bc[ni][1] = bias_scale * __ldg(&bias[col + 1]);
    }
    #pragma unroll
    for (int mi = 0; mi < 2; mi++) {
        const int row = m0 + wm * 32 + mi * 16 + (lane >> 2);
        #pragma unroll
        for (int ni = 0; ni < 8; ni++) {
            const int col = n0 + wn * 64 + ni * 8 + (lane & 3) * 2;
            if constexpr (sizeof(OutT) == 2) {
                const __half2 h0 = __floats2half2_rn(acc[mi][ni][0] + bc[ni][0], acc[mi][ni][1] + bc[ni][1]);
                const __half2 h1 = __floats2half2_rn(acc[mi][ni][2] + bc[ni][0], acc[mi][ni][3] + bc[ni][1]);
                __stcs((__half2*)&C[(size_t)row * N + col], h0);
                __stcs((__half2*)&C[(size_t)(row + 8) * N + col], h1);
            } else {
                const float2 f0 = { acc[mi][ni][0] + bc[ni][0], acc[mi][ni][1] + bc[ni][1] };
                const float2 f1 = { acc[mi][ni][2] + bc[ni][0], acc[mi][ni][3] + bc[ni][1] };
                __stcs((float2*)&C[(size_t)row * N + col], f0);
                __stcs((float2*)&C[(size_t)(row + 8) * N + col], f1);
            }
        }
    }
}

// ---------------- fp32 -> fp16 convert --------------------------------------
__global__ void __launch_bounds__(256)
f2h_kernel(const float* __restrict__ in, __half* __restrict__ out, int n8)
{
    for (int i = blockIdx.x * blockDim.x + threadIdx.x; i < n8; i += gridDim.x * blockDim.x) {
        const float4 v0 = ((const float4*)in)[i * 2];
        const float4 v1 = ((const float4*)in)[i * 2 + 1];
        __half2 h[4];
        h[0] = __floats2half2_rn(v0.x, v0.y);
        h[1] = __floats2half2_rn(v0.z, v0.w);
        h[2] = __floats2half2_rn(v1.x, v1.y);
        h[3] = __floats2half2_rn(v1.z, v1.w);
        ((uint4*)out)[i] = *(uint4*)h;
    }
}

// ---------------- transpose + fp16 convert ----------------------------------
__global__ void __launch_bounds__(256)
transpose_h_kernel(const float* __restrict__ in, __half* __restrict__ out, int R, int Cc)
{
    __shared__ float t[32][33];
    const int tx = threadIdx.x & 31, ty = threadIdx.x >> 5;
    const int bx = blockIdx.x * 32, by = blockIdx.y * 32;
    #pragma unroll
    for (int j = 0; j < 4; j++)
        t[ty + j * 8][tx] = in[(size_t)(by + ty + j * 8) * Cc + bx + tx];
    __syncthreads();
    #pragma unroll
    for (int j = 0; j < 4; j++)
        out[(size_t)(bx + ty + j * 8) * R + by + tx] = __float2half_rn(t[tx][ty + j * 8]);
}

// ---------------------------------------------------------------------------
// K2: warp-per-token attention + head collapse (proven R8 version)
// ---------------------------------------------------------------------------
#define W_PART 2176
#define W_WB   6528
#define W_SZ   6560
#define ATTN_SMEM (4 * W_SZ * 2)    // 52480 B, 4 warps/CTA

__global__ void __launch_bounds__(128)
attn_kernel(const __half* __restrict__ qkv, __half* __restrict__ s_out)
{
    extern __shared__ __half asm_[];
    const int lane = threadIdx.x & 31;
    const int warp = threadIdx.x >> 5;
    const int tok  = blockIdx.x * 4 + warp;

    __half* base = asm_ + warp * W_SZ;
    const __half* src = qkv + (size_t)tok * QKV_DIM;

    #pragma unroll
    for (int i = 0; i < 24; i++) {
        const int c = i * 32 + lane;
        const int part = c >> 8;
        const int rem = c & 255, r = rem >> 4, j = rem & 15;
        cp_async16(base + part * W_PART + r * 136 + j * 8,
                   src + part * 2048 + r * 128 + j * 8);
    }
    cp_commit();
    cp_wait<0>();
    __syncwarp();

    float sacc[2][4] = {{0,0,0,0},{0,0,0,0}};
    const int a_row = lane & 15;
    const int a_col = (lane >> 4) * 8;
    const int b_row = ((lane >> 4) << 3) + (lane & 7);
    const int b_col = ((lane >> 3) & 1) * 8;
    #pragma unroll
    for (int ks = 0; ks < 8; ks++) {
        uint32_t af[4], bf[4];
        ldsm_x4(af, base + a_row * 136 + a_col + ks * 16);
        ldsm_x4(bf, base + W_PART + b_row * 136 + b_col + ks * 16);
        mma_f16(sacc[0], af, &bf[0]);
        mma_f16(sacc[1], af, &bf[2]);
    }

    const float scale = 0.08838834764831844f;
    float a0 = sacc[0][0] * scale, a1 = sacc[0][1] * scale;
    float a2 = sacc[1][0] * scale, a3 = sacc[1][1] * scale;
    float b0 = sacc[0][2] * scale, b1 = sacc[0][3] * scale;
    float b2 = sacc[1][2] * scale, b3 = sacc[1][3] * scale;

    float mA = fmaxf(fmaxf(a0, a1), fmaxf(a2, a3));
    float mB = fmaxf(fmaxf(b0, b1), fmaxf(b2, b3));
    #pragma unroll
    for (int off = 1; off <= 2; off <<= 1) {
        mA = fmaxf(mA, __shfl_xor_sync(0xffffffffu, mA, off));
        mB = fmaxf(mB, __shfl_xor_sync(0xffffffffu, mB, off));
    }
    a0 = __expf(a0 - mA); a1 = __expf(a1 - mA); a2 = __expf(a2 - mA); a3 = __expf(a3 - mA);
    b0 = __expf(b0 - mB); b1 = __expf(b1 - mB); b2 = __expf(b2 - mB); b3 = __expf(b3 - mB);
    float sA = a0 + a1 + a2 + a3, sB = b0 + b1 + b2 + b3;
    #pragma unroll
    for (int off = 1; off <= 2; off <<= 1) {
        sA += __shfl_xor_sync(0xffffffffu, sA, off);
        sB += __shfl_xor_sync(0xffffffffu, sB, off);
    }
    const float rA = __fdividef(1.0f, sA), rB = __fdividef(1.0f, sB);

    float cs0 = a0 * rA + b0 * rB;
    float cs1 = a1 * rA + b1 * rB;
    float cs2 = a2 * rA + b2 * rB;
    float cs3 = a3 * rA + b3 * rB;
    #pragma unroll
    for (int off = 4; off <= 16; off <<= 1) {
        cs0 += __shfl_xor_sync(0xffffffffu, cs0, off);
        cs1 += __shfl_xor_sync(0xffffffffu, cs1, off);
        cs2 += __shfl_xor_sync(0xffffffffu, cs2, off);
        cs3 += __shfl_xor_sync(0xffffffffu, cs3, off);
    }
    float* wb = (float*)(base + W_WB);
    if (lane < 4) {
        wb[2 * lane]     = cs0;
        wb[2 * lane + 1] = cs1;
        wb[8 + 2 * lane] = cs2;
        wb[9 + 2 * lane] = cs3;
    }
    __syncwarp();

    const __half2* V2 = (const __half2*)(base + 2 * W_PART);
    float2 o0 = {0.f, 0.f}, o1 = {0.f, 0.f};
    #pragma unroll
    for (int g = 0; g < 16; g++) {
        const float wg = wb[g];
        const float2 f0 = __half22float2(V2[g * 68 + lane]);
        const float2 f1 = __half22float2(V2[g * 68 + lane + 32]);
        o0.x += wg * f0.x; o0.y += wg * f0.y;
        o1.x += wg * f1.x; o1.y += wg * f1.y;
    }
    __half2* o = (__half2*)(s_out + (size_t)tok * HD);
    o[lane]      = __floats2half2_rn(o0.x, o0.y);
    o[lane + 32] = __floats2half2_rn(o1.x, o1.y);
}

// ---------------- launch ------------------------------------------------------
extern "C" void kernel_launch(void* const* d_in, const int* in_sizes, int n_in,
                              void* d_out, int out_size)
{
    const float* x      = (const float*)d_in[0];
    const float* W_pre  = (const float*)d_in[1];
    const float* b_pre  = (const float*)d_in[2];
    const float* W_proj = (const float*)d_in[3];
    const float* b_proj = (const float*)d_in[4];
    float* out = (float*)d_out;

    const int M = in_sizes[0] / IN_DIM;   // 32768

    __half *qkv, *sh, *xh, *wth, *wpth;
    cudaGetSymbolAddress((void**)&qkv,  g_qkv);
    cudaGetSymbolAddress((void**)&sh,   g_sh);
    cudaGetSymbolAddress((void**)&xh,   g_xh);
    cudaGetSymbolAddress((void**)&wth,  g_wth);
    cudaGetSymbolAddress((void**)&wpth, g_wpth);

    static bool attr_set = false;
    if (!attr_set) {
        cudaFuncSetAttribute(gemm_f16_kernel<__half>,
                             cudaFuncAttributeMaxDynamicSharedMemorySize, GEMM_SMEM);
        cudaFuncSetAttribute(gemm_f16_kernel<float>,
                             cudaFuncAttributeMaxDynamicSharedMemorySize, GEMM_SMEM);
        cudaFuncSetAttribute(attn_kernel,
                             cudaFuncAttributeMaxDynamicSharedMemorySize, ATTN_SMEM);
        attr_set = true;
    }

    // prep
    f2h_kernel<<<1024, 256>>>(x, xh, M * IN_DIM / 8);
    transpose_h_kernel<<<dim3(QKV_DIM / 32, IN_DIM / 32), 256>>>(W_pre, wth, IN_DIM, QKV_DIM);
    transpose_h_kernel<<<dim3(OUT_DIM / 32, HD / 32), 256>>>(W_proj, wpth, HD, OUT_DIM);

    // K1: qkv = x @ W_pre + b_pre            [M, 6144] half
    gemm_f16_kernel<__half><<<dim3(QKV_DIM / BN, M / BM), 256, GEMM_SMEM>>>(
        xh, wth, b_pre, 1.0f, qkv, M, QKV_DIM, IN_DIM);

    // K2: attention collapse -> s[M,128] (half), warp-per-token
    attn_kernel<<<M / 4, 128, ATTN_SMEM>>>(qkv, sh);

    // K3: out = s @ W_proj + 16*b_proj       [M, 1024] fp32
    gemm_f16_kernel<float><<<dim3(OUT_DIM / BN, M / BM), 256, GEMM_SMEM>>>(
        sh, wpth, b_proj, 16.0f, out, M, OUT_DIM, HD);
}